// round 8
// baseline (speedup 1.0000x reference)
#include <cuda_runtime.h>
#include <cuda_bf16.h>
#include <math.h>

#define BB   256
#define TT   128
#define LL   64
#define EENC 512
#define DD   512
#define EMBW 128
#define AA   129
#define ATTH 20

#define NT   512

#define PIT    40                  // smem row pitch in bf16 (80B, ldsm conflict-free)
#define MATSZ  (64 * PIT)          // one 64x32 staged matrix (2560 elems)
#define STGE   (8 * MATSZ)         // one K=64 stage: two k-halves x (Ah,Al,Wh,Wl)
#define RING   4
#define SMEM_BYTES (RING * STGE * 2)   // 163840 B

typedef unsigned int u32;
typedef __nv_bfloat16 bf;

// ---------------- device scratch (static, no allocs) ----------------
__device__ __align__(16) bf    g_eseq_h[TT * BB * EMBW];
__device__ __align__(16) bf    g_eseq_l[TT * BB * EMBW];
__device__ __align__(16) float g_encatt[BB * LL * ATTH];
__device__ __align__(16) bf    g_att_h[BB * DD],  g_att_l[BB * DD];
__device__ __align__(16) float g_hf[3][2][BB * DD];
__device__ __align__(16) bf    g_hh[3][2][BB * DD], g_hl[3][2][BB * DD];
__device__ __align__(16) float g_c[3][BB * DD];
__device__ __align__(16) bf    g_ctx_h[BB * EENC], g_ctx_l[BB * EENC];
__device__ __align__(16) bf    g_act1_h[BB * DD],  g_act1_l[BB * DD];

__device__ __align__(16) bf g_Wc_h[DD * (EMBW + EENC)],  g_Wc_l[DD * (EMBW + EENC)];
__device__ __align__(16) bf g_Wih_h[3][4 * DD * DD], g_Wih_l[3][4 * DD * DD];
__device__ __align__(16) bf g_Whh_h[3][4 * DD * DD], g_Whh_l[3][4 * DD * DD];
__device__ __align__(16) bf g_Wl1_h[DD * (DD + EENC)], g_Wl1_l[DD * (DD + EENC)];
__device__ __align__(16) bf g_Wl2_h[AA * DD], g_Wl2_l[AA * DD];

__device__ unsigned int g_bar_count = 0;
__device__ unsigned int g_bar_gen   = 0;

// ---------------- helpers ----------------
__device__ __forceinline__ void split_bf(float x, bf& h, bf& l) {
    h = __float2bfloat16(x);
    l = __float2bfloat16(x - __bfloat162float(h));
}
__device__ __forceinline__ u32 sptr(const void* p) {
    return (u32)__cvta_generic_to_shared(p);
}
__device__ __forceinline__ void ldsm4(u32* r, u32 a) {
    asm volatile("ldmatrix.sync.aligned.m8n8.x4.shared.b16 {%0,%1,%2,%3}, [%4];"
                 : "=r"(r[0]), "=r"(r[1]), "=r"(r[2]), "=r"(r[3]) : "r"(a));
}
__device__ __forceinline__ void mma16816(float* d, const u32* a, const u32* b) {
    asm volatile(
        "mma.sync.aligned.m16n8k16.row.col.f32.bf16.bf16.f32 "
        "{%0,%1,%2,%3},{%4,%5,%6,%7},{%8,%9},{%0,%1,%2,%3};"
        : "+f"(d[0]), "+f"(d[1]), "+f"(d[2]), "+f"(d[3])
        : "r"(a[0]), "r"(a[1]), "r"(a[2]), "r"(a[3]), "r"(b[0]), "r"(b[1]));
}
__device__ __forceinline__ void cpa(u32 dst, const void* src, int sz) {
    asm volatile("cp.async.cg.shared.global [%0], [%1], 16, %2;"
                 :: "r"(dst), "l"(src), "r"(sz));
}
__device__ __forceinline__ void cp_commit() {
    asm volatile("cp.async.commit_group;" ::: "memory");
}
__device__ __forceinline__ void cp_wait2() {
    asm volatile("cp.async.wait_group 2;" ::: "memory");
}
#define HBAR(id) asm volatile("bar.sync %0, 256;" :: "r"(id) : "memory")

// ---------------- launch-reentrant grid barrier ----------------
__device__ __forceinline__ void gsync(int nb) {
    __syncthreads();
    if (threadIdx.x == 0) {
        __threadfence();
        unsigned int gen = *(volatile unsigned int*)&g_bar_gen;
        if (atomicAdd(&g_bar_count, 1u) == (unsigned int)(nb - 1)) {
            g_bar_count = 0;
            __threadfence();
            atomicAdd(&g_bar_gen, 1u);
        } else {
            while (*(volatile unsigned int*)&g_bar_gen == gen) { }
        }
        __threadfence();
    }
    __syncthreads();
}

// ---------------- 32-K sub-stage compute ----------------
__device__ __forceinline__ void stage_mma(bf* buf, int wm, int wn, int lane,
                                          float acc[2][4]) {
#pragma unroll
    for (int q = 0; q < 2; q++) {
        u32 ah[4], al[4], bh[4], bl[4];
        u32 abase = sptr(buf + (wm * 16 + (lane & 15)) * PIT
                             + q * 16 + ((lane >> 4) & 1) * 8);
        ldsm4(ah, abase);
        ldsm4(al, abase + MATSZ * 2);
        u32 bbase = sptr(buf + 2 * MATSZ
                             + (wn * 16 + (lane & 7) + ((lane >> 4) & 1) * 8) * PIT
                             + q * 16 + ((lane >> 3) & 1) * 8);
        ldsm4(bh, bbase);
        ldsm4(bl, bbase + MATSZ * 2);
        mma16816(acc[0], ah, bh + 0);
        mma16816(acc[1], ah, bh + 2);
        mma16816(acc[0], ah, bl + 0);
        mma16816(acc[1], ah, bl + 2);
        mma16816(acc[0], al, bh + 0);
        mma16816(acc[1], al, bh + 2);
    }
}

// ---------------- generic 64x64 mma tile: C = [A1|A2] @ W^T + bias ----------------
// K multiples of 64; K1 % 64 == 0.
__device__ __forceinline__ void mm_tile(
    bf* stg, int tile,
    const bf* __restrict__ A1h, const bf* __restrict__ A1l, int K1,
    const bf* __restrict__ A2h, const bf* __restrict__ A2l, int K2,
    const bf* __restrict__ Wh,  const bf* __restrict__ Wl, int ldw, int N,
    const float* __restrict__ bias, int relu,
    float* __restrict__ Cf, size_t ldc,
    bf* __restrict__ Ch, bf* __restrict__ Cl, int ldcb)
{
    __syncthreads();
    const int tid = threadIdx.x;
    const int lane = tid & 31, warp = tid >> 5;
    const int wm = warp >> 2, wn = warp & 3;
    const int ntN = (N + 63) >> 6;
    const int m0 = (tile / ntN) * 64, n0 = (tile % ntN) * 64;
    const int S = (K1 + K2) >> 6;          // K=64 stages

    const int smat = tid >> 8;             // 0=hi, 1=lo
    const int srow = (tid >> 2) & 63;
    const int schk = tid & 3;
    const int wrow = n0 + srow;
    const int wsz  = (wrow < N) ? 16 : 0;
    const int wr_c = (wrow < N) ? wrow : 0;

    float acc[2][4] = {};

    auto issue = [&](int s) {
        bf* buf = stg + (s & 3) * STGE;
#pragma unroll
        for (int h32 = 0; h32 < 2; h32++) {
            int kb = (s << 6) + h32 * 32;
            const bf* Ap; int lda, ka;
            if (kb < K1) { Ap = smat ? A1l : A1h; lda = K1; ka = kb; }
            else         { Ap = smat ? A2l : A2h; lda = K2; ka = kb - K1; }
            bf* sub = buf + h32 * (4 * MATSZ);
            u32 da = sptr(sub + smat * MATSZ + srow * PIT + schk * 8);
            u32 dw = sptr(sub + (2 + smat) * MATSZ + srow * PIT + schk * 8);
            cpa(da, Ap + (size_t)(m0 + srow) * lda + ka + schk * 8, 16);
            const bf* Wp = smat ? Wl : Wh;
            cpa(dw, Wp + (size_t)wr_c * ldw + kb + schk * 8, wsz);
        }
    };

    if (0 < S) issue(0);
    cp_commit();
    if (1 < S) issue(1);
    cp_commit();
    if (2 < S) issue(2);
    cp_commit();

    for (int s = 0; s < S; s++) {
        cp_wait2();
        __syncthreads();
        if (s + 3 < S) issue(s + 3);
        cp_commit();
        bf* buf = stg + (s & 3) * STGE;
        stage_mma(buf, wm, wn, lane, acc);
        stage_mma(buf + 4 * MATSZ, wm, wn, lane, acc);
    }

    // epilogue
#pragma unroll
    for (int bb = 0; bb < 2; bb++) {
        int nc = n0 + wn * 16 + bb * 8 + (lane & 3) * 2;
        int r0 = m0 + wm * 16 + (lane >> 2);
#pragma unroll
        for (int hf = 0; hf < 2; hf++) {
            int r = r0 + hf * 8;
#pragma unroll
            for (int j = 0; j < 2; j++) {
                int n = nc + j;
                if (n < N) {
                    float v = acc[bb][hf * 2 + j] + bias[n];
                    if (relu) v = fmaxf(v, 0.f);
                    if (Cf) Cf[(size_t)r * ldc + n] = v;
                    if (Ch) {
                        bf vh, vl; split_bf(v, vh, vl);
                        Ch[(size_t)r * ldcb + n] = vh;
                        Cl[(size_t)r * ldcb + n] = vl;
                    }
                }
            }
        }
    }
}

// ---------------- LSTM 64x64 mma tile: gate remap + fused pointwise ----------
__device__ __forceinline__ void lstm_mma(
    bf* stg, int tile,
    const bf* __restrict__ xh, const bf* __restrict__ xl,
    const bf* __restrict__ hhx, const bf* __restrict__ hlx,
    const bf* __restrict__ Wihh, const bf* __restrict__ Wihl,
    const bf* __restrict__ Whhh, const bf* __restrict__ Whhl,
    const float* __restrict__ bih, const float* __restrict__ bhh,
    float* __restrict__ houtf, bf* __restrict__ houth, bf* __restrict__ houtl,
    float* __restrict__ cbuf)
{
    __syncthreads();
    const int tid = threadIdx.x;
    const int lane = tid & 31, warp = tid >> 5;
    const int wm = warp >> 2, wn = warp & 3;
    const int m0 = (tile >> 5) * 64;
    const int d0 = (tile & 31) * 16;

    const int smat = tid >> 8;
    const int srow = (tid >> 2) & 63;
    const int schk = tid & 3;
    const int wrow = ((srow >> 4) << 9) + d0 + (srow & 15);   // gate*512 + d

    float acc[2][4] = {};

    auto issue = [&](int s) {           // s in [0,16): K=64 per stage
        const bf* Ap = (s < 8) ? (smat ? xl : xh) : (smat ? hlx : hhx);
        const bf* Wp = (s < 8) ? (smat ? Wihl : Wihh) : (smat ? Whhl : Whhh);
        int kb0 = (s & 7) * 64;
        bf* buf = stg + (s & 3) * STGE;
#pragma unroll
        for (int h32 = 0; h32 < 2; h32++) {
            int kb = kb0 + h32 * 32;
            bf* sub = buf + h32 * (4 * MATSZ);
            u32 da = sptr(sub + smat * MATSZ + srow * PIT + schk * 8);
            u32 dw = sptr(sub + (2 + smat) * MATSZ + srow * PIT + schk * 8);
            cpa(da, Ap + (size_t)(m0 + srow) * 512 + kb + schk * 8, 16);
            cpa(dw, Wp + (size_t)wrow * 512 + kb + schk * 8, 16);
        }
    };

    issue(0); cp_commit();
    issue(1); cp_commit();
    issue(2); cp_commit();

    for (int s = 0; s < 16; s++) {
        cp_wait2();
        __syncthreads();
        if (s + 3 < 16) issue(s + 3);
        cp_commit();
        bf* buf = stg + (s & 3) * STGE;
        stage_mma(buf, wm, wn, lane, acc);
        stage_mma(buf + 4 * MATSZ, wm, wn, lane, acc);
    }

    // dump C frags to smem G[64][68] (slot 0; last compute read slot 3)
    float* G = (float*)stg;
#pragma unroll
    for (int bb = 0; bb < 2; bb++) {
        int c = wn * 16 + bb * 8 + (lane & 3) * 2;
        int r0 = wm * 16 + (lane >> 2);
        *(float2*)(G + r0 * 68 + c)       = make_float2(acc[bb][0], acc[bb][1]);
        *(float2*)(G + (r0 + 8) * 68 + c) = make_float2(acc[bb][2], acc[bb][3]);
    }
    __syncthreads();

    for (int e = tid; e < 1024; e += NT) {
        int m = e & 63, dp = e >> 6;
        int d = d0 + dp;
        const float* Gm = G + m * 68;
        float gi = Gm[dp]      + bih[d]        + bhh[d];
        float gf = Gm[16 + dp] + bih[512 + d]  + bhh[512 + d];
        float gg = Gm[32 + dp] + bih[1024 + d] + bhh[1024 + d];
        float go = Gm[48 + dp] + bih[1536 + d] + bhh[1536 + d];
        size_t idx = (size_t)(m0 + m) * 512 + d;
        float si = 1.f / (1.f + expf(-gi));
        float sf = 1.f / (1.f + expf(-gf));
        float so = 1.f / (1.f + expf(-go));
        float cn = sf * cbuf[idx] + si * tanhf(gg);
        cbuf[idx] = cn;
        float hn = so * tanhf(cn);
        houtf[idx] = hn;
        bf vh, vl; split_bf(hn, vh, vl);
        houth[idx] = vh;
        houtl[idx] = vl;
    }
}

// ---------------- kernel params ----------------
struct Params {
    const int* act;
    const float* enc;
    const float* enc_h;
    const float* enc_c;
    const float* embW;
    const float* Wc;  const float* bc;
    const float* Wih[3]; const float* Whh[3];
    const float* bih[3]; const float* bhh[3];
    const float* Wa1; const float* ba1;
    const float* Wa2; const float* ba2;
    const float* Wl1; const float* bl1;
    const float* Wl2; const float* bl2;
    float* out;
};

// ---------------- persistent mega-kernel ----------------
__global__ void __launch_bounds__(NT, 1) decoder_kernel(Params p)
{
    extern __shared__ __align__(16) bf stg[];
    const int nb  = gridDim.x;
    const int bid = blockIdx.x;
    const int tid = threadIdx.x;
    const int gt = bid * NT + tid, gs = nb * NT;

    // ---- phase 0: setup ----
    for (int idx = gt; idx < BB * DD; idx += gs) {
        float h = p.enc_h[idx], c = p.enc_c[idx];
        bf vh, vl; split_bf(h, vh, vl);
#pragma unroll
        for (int cc = 0; cc < 3; cc++) {
            g_hf[cc][0][idx] = h;
            g_hh[cc][0][idx] = vh; g_hl[cc][0][idx] = vl;
            g_c[cc][idx] = c;
        }
        g_ctx_h[idx] = __float2bfloat16(0.f);
        g_ctx_l[idx] = __float2bfloat16(0.f);
    }
    for (int i4 = gt; i4 < TT * BB * EMBW / 4; i4 += gs) {
        int row = i4 >> 5;
        int kq  = i4 & 31;
        int t = row >> 8;
        int b = row & 255;
        float4 v = make_float4(0.f, 0.f, 0.f, 0.f);
        if (t > 0) {
            int a = p.act[b * TT + t - 1];
            v = *(const float4*)(p.embW + (size_t)a * EMBW + kq * 4);
        }
        size_t base = (size_t)row * EMBW + kq * 4;
        bf vh, vl;
        split_bf(v.x, vh, vl); g_eseq_h[base + 0] = vh; g_eseq_l[base + 0] = vl;
        split_bf(v.y, vh, vl); g_eseq_h[base + 1] = vh; g_eseq_l[base + 1] = vl;
        split_bf(v.z, vh, vl); g_eseq_h[base + 2] = vh; g_eseq_l[base + 2] = vl;
        split_bf(v.w, vh, vl); g_eseq_h[base + 3] = vh; g_eseq_l[base + 3] = vl;
    }
    for (int i = gt; i < DD * (EMBW + EENC); i += gs) {
        bf vh, vl; split_bf(p.Wc[i], vh, vl);
        g_Wc_h[i] = vh; g_Wc_l[i] = vl;
    }
#pragma unroll
    for (int cc = 0; cc < 3; cc++) {
        for (int i = gt; i < 4 * DD * DD; i += gs) {
            bf vh, vl;
            split_bf(p.Wih[cc][i], vh, vl); g_Wih_h[cc][i] = vh; g_Wih_l[cc][i] = vl;
            split_bf(p.Whh[cc][i], vh, vl); g_Whh_h[cc][i] = vh; g_Whh_l[cc][i] = vl;
        }
    }
    for (int i = gt; i < DD * (DD + EENC); i += gs) {
        bf vh, vl; split_bf(p.Wl1[i], vh, vl);
        g_Wl1_h[i] = vh; g_Wl1_l[i] = vl;
    }
    for (int i = gt; i < AA * DD; i += gs) {
        bf vh, vl; split_bf(p.Wl2[i], vh, vl);
        g_Wl2_h[i] = vh; g_Wl2_l[i] = vl;
    }
    {
        int lane = tid & 31;
        int gw0 = gt >> 5;
        for (int gw = gw0; gw < BB * LL; gw += gs >> 5) {
            const float* er = p.enc + (size_t)gw * EENC;
            float r[16];
#pragma unroll
            for (int i = 0; i < 16; i++) r[i] = er[lane + 32 * i];
            for (int j = 0; j < ATTH; j++) {
                const float* w = p.Wa1 + (size_t)j * (EENC + DD);
                float s = 0.f;
#pragma unroll
                for (int i = 0; i < 16; i++) s += r[i] * w[lane + 32 * i];
#pragma unroll
                for (int o = 16; o; o >>= 1) s += __shfl_xor_sync(0xFFFFFFFFu, s, o);
                if (lane == 0) g_encatt[(size_t)gw * ATTH + j] = s + p.ba1[j];
            }
        }
    }
    gsync(nb);

    // ---- att for t=0 ----
    for (int u = bid; u < 32; u += nb)
        mm_tile(stg, u, g_eseq_h, g_eseq_l, EMBW, g_ctx_h, g_ctx_l, EENC,
                g_Wc_h, g_Wc_l, EMBW + EENC, DD, p.bc, 0,
                (float*)0, 0, g_att_h, g_att_l, DD);
    gsync(nb);

    // ---- main loop ----
    for (int t = 0; t < TT; t++) {
        const int cur = t & 1, nxt = cur ^ 1;

        // Phase A: LSTM cell0 (+ logits of t-1, independent)
        {
            const int ntA = 128 + (t > 0 ? 12 : 0);
            for (int u = bid; u < ntA; u += nb) {
                if (u < 128)
                    lstm_mma(stg, u, g_att_h, g_att_l,
                             g_hh[0][cur], g_hl[0][cur],
                             g_Wih_h[0], g_Wih_l[0], g_Whh_h[0], g_Whh_l[0],
                             p.bih[0], p.bhh[0],
                             g_hf[0][nxt], g_hh[0][nxt], g_hl[0][nxt], g_c[0]);
                else
                    mm_tile(stg, u - 128, g_act1_h, g_act1_l, DD,
                            (const bf*)0, (const bf*)0, 0,
                            g_Wl2_h, g_Wl2_l, DD, AA, p.bl2, 0,
                            p.out + (size_t)(t - 1) * AA, (size_t)TT * AA,
                            (bf*)0, (bf*)0, 0);
            }
            gsync(nb);
        }

        // Phases B, C: cells 1, 2
        for (int cell = 1; cell < 3; cell++) {
            for (int u = bid; u < 128; u += nb)
                lstm_mma(stg, u, g_hh[cell - 1][nxt], g_hl[cell - 1][nxt],
                         g_hh[cell][cur], g_hl[cell][cur],
                         g_Wih_h[cell], g_Wih_l[cell],
                         g_Whh_h[cell], g_Whh_l[cell],
                         p.bih[cell], p.bhh[cell],
                         g_hf[cell][nxt], g_hh[cell][nxt], g_hl[cell][nxt],
                         g_c[cell]);
            gsync(nb);
        }

        // Phase D: attention, 2 rows/block via half-block barriers
        __syncthreads();
        {
            const int half = tid >> 8;
            const int htid = tid & 255;
            const int barid = 1 + half;
            float* smf = (float*)stg + half * 2048;
            const int warp8 = htid >> 5, lane = htid & 31;
            for (int b = bid * 2 + half; b < BB; b += nb * 2) {
                float* sh_h  = smf;
                float* sh_hp = smf + 512;
                float* sh_s  = smf + 544;
                const float* h2 = g_hf[2][nxt];
                for (int k = htid; k < DD; k += 256) sh_h[k] = h2[(size_t)b * DD + k];
                HBAR(barid);
                for (int j = warp8; j < ATTH; j += 8) {
                    const float* w = p.Wa1 + (size_t)j * (EENC + DD) + EENC;
                    float s = 0.f;
                    for (int k = lane; k < DD; k += 32) s += sh_h[k] * w[k];
#pragma unroll
                    for (int o = 16; o; o >>= 1) s += __shfl_xor_sync(0xFFFFFFFFu, s, o);
                    if (lane == 0) sh_hp[j] = s;
                }
                HBAR(barid);
                if (htid < LL) {
                    const float* ea = g_encatt + ((size_t)b * LL + htid) * ATTH;
                    float s = 0.f;
#pragma unroll
                    for (int j = 0; j < ATTH; j++) {
                        float v = ea[j] + sh_hp[j];
                        v = v > 0.f ? v : 0.f;
                        s += v * p.Wa2[j];
                    }
                    sh_s[htid] = tanhf(s + p.ba2[0]);
                }
                HBAR(barid);
                if (warp8 == 0) {
                    float v0 = sh_s[lane], v1 = sh_s[lane + 32];
                    float m = fmaxf(v0, v1);
#pragma unroll
                    for (int o = 16; o; o >>= 1) m = fmaxf(m, __shfl_xor_sync(0xFFFFFFFFu, m, o));
                    float e0 = expf(v0 - m), e1 = expf(v1 - m);
                    float sum = e0 + e1;
#pragma unroll
                    for (int o = 16; o; o >>= 1) sum += __shfl_xor_sync(0xFFFFFFFFu, sum, o);
                    float inv = 1.f / sum;
                    sh_s[lane] = e0 * inv;
                    sh_s[lane + 32] = e1 * inv;
                }
                HBAR(barid);
                const float* eb = p.enc + (size_t)b * LL * EENC;
                for (int k = htid; k < EENC; k += 256) {
                    float s = 0.f;
#pragma unroll 8
                    for (int l = 0; l < LL; l++) s += sh_s[l] * eb[(size_t)l * EENC + k];
                    bf vh, vl; split_bf(s, vh, vl);
                    g_ctx_h[(size_t)b * EENC + k] = vh;
                    g_ctx_l[(size_t)b * EENC + k] = vl;
                }
            }
        }
        gsync(nb);

        // Phase E: Wl1 + att(t+1) — independent given ctx
        {
            const int ntE = 32 + ((t + 1 < TT) ? 32 : 0);
            for (int u = bid; u < ntE; u += nb) {
                if (u < 32)
                    mm_tile(stg, u, g_hh[2][nxt], g_hl[2][nxt], DD,
                            g_ctx_h, g_ctx_l, EENC,
                            g_Wl1_h, g_Wl1_l, DD + EENC, DD, p.bl1, 1,
                            (float*)0, 0, g_act1_h, g_act1_l, DD);
                else
                    mm_tile(stg, u - 32,
                            g_eseq_h + (size_t)(t + 1) * BB * EMBW,
                            g_eseq_l + (size_t)(t + 1) * BB * EMBW, EMBW,
                            g_ctx_h, g_ctx_l, EENC,
                            g_Wc_h, g_Wc_l, EMBW + EENC, DD, p.bc, 0,
                            (float*)0, 0, g_att_h, g_att_l, DD);
            }
            gsync(nb);
        }
    }

    // final logits (t = TT-1)
    for (int u = bid; u < 12; u += nb)
        mm_tile(stg, u, g_act1_h, g_act1_l, DD, (const bf*)0, (const bf*)0, 0,
                g_Wl2_h, g_Wl2_l, DD, AA, p.bl2, 0,
                p.out + (size_t)(TT - 1) * AA, (size_t)TT * AA,
                (bf*)0, (bf*)0, 0);
}

// ---------------- host ----------------
extern "C" void kernel_launch(void* const* d_in, const int* in_sizes, int n_in,
                              void* d_out, int out_size)
{
    Params p;
    p.act    = (const int*)  d_in[0];
    p.enc    = (const float*)d_in[1];
    p.enc_h  = (const float*)d_in[2];
    p.enc_c  = (const float*)d_in[3];
    p.embW   = (const float*)d_in[4];
    p.Wc     = (const float*)d_in[5];
    p.bc     = (const float*)d_in[6];
    p.Wih[0] = (const float*)d_in[7];  p.Whh[0] = (const float*)d_in[8];
    p.bih[0] = (const float*)d_in[9];  p.bhh[0] = (const float*)d_in[10];
    p.Wih[1] = (const float*)d_in[11]; p.Whh[1] = (const float*)d_in[12];
    p.bih[1] = (const float*)d_in[13]; p.bhh[1] = (const float*)d_in[14];
    p.Wih[2] = (const float*)d_in[15]; p.Whh[2] = (const float*)d_in[16];
    p.bih[2] = (const float*)d_in[17]; p.bhh[2] = (const float*)d_in[18];
    p.Wa1 = (const float*)d_in[19]; p.ba1 = (const float*)d_in[20];
    p.Wa2 = (const float*)d_in[21]; p.ba2 = (const float*)d_in[22];
    p.Wl1 = (const float*)d_in[23]; p.bl1 = (const float*)d_in[24];
    p.Wl2 = (const float*)d_in[25]; p.bl2 = (const float*)d_in[26];
    p.out = (float*)d_out;

    int dev = 0;
    cudaGetDevice(&dev);
    int nsm = 0;
    cudaDeviceGetAttribute(&nsm, cudaDevAttrMultiProcessorCount, dev);
    if (nsm <= 0) nsm = 148;

    cudaFuncSetAttribute(decoder_kernel,
                         cudaFuncAttributeMaxDynamicSharedMemorySize, SMEM_BYTES);
    decoder_kernel<<<nsm, NT, SMEM_BYTES>>>(p);
}

// round 9
// speedup vs baseline: 1.0996x; 1.0996x over previous
#include <cuda_runtime.h>
#include <cuda_bf16.h>
#include <math.h>

#define BB   256
#define TT   128
#define LL   64
#define EENC 512
#define DD   512
#define EMBW 128
#define AA   129
#define ATTH 20

#define NT   512

#define PIT    40                  // smem row pitch in bf16 (80B, ldsm conflict-free)
#define MATSZ  (64 * PIT)          // one 64x32 staged matrix (2560 elems)
#define BUFE   (4 * MATSZ)         // Ahi, Alo, Whi, Wlo per stage (10240 elems)
#define RING   4
#define SMEM_BYTES (RING * BUFE * 2)   // 81920 B

typedef unsigned int u32;
typedef __nv_bfloat16 bf;

// ---------------- device scratch (static, no allocs) ----------------
__device__ __align__(16) bf    g_eseq_h[TT * BB * EMBW];
__device__ __align__(16) bf    g_eseq_l[TT * BB * EMBW];
__device__ __align__(16) float g_encatt[BB * LL * ATTH];
__device__ __align__(16) bf    g_att_h[BB * DD],  g_att_l[BB * DD];
__device__ __align__(16) float g_hf[3][2][BB * DD];
__device__ __align__(16) bf    g_hh[3][2][BB * DD], g_hl[3][2][BB * DD];
__device__ __align__(16) float g_c[3][BB * DD];
__device__ __align__(16) bf    g_ctx_h[BB * EENC], g_ctx_l[BB * EENC];
__device__ __align__(16) bf    g_act1_h[BB * DD],  g_act1_l[BB * DD];

__device__ __align__(16) bf g_Wc_h[DD * (EMBW + EENC)],  g_Wc_l[DD * (EMBW + EENC)];
__device__ __align__(16) bf g_Wih_h[3][4 * DD * DD], g_Wih_l[3][4 * DD * DD];
__device__ __align__(16) bf g_Whh_h[3][4 * DD * DD], g_Whh_l[3][4 * DD * DD];
__device__ __align__(16) bf g_Wl1_h[DD * (DD + EENC)], g_Wl1_l[DD * (DD + EENC)];
__device__ __align__(16) bf g_Wl2_h[AA * DD], g_Wl2_l[AA * DD];

__device__ unsigned int g_bar_count = 0;
__device__ unsigned int g_bar_gen   = 0;

// ---------------- helpers ----------------
__device__ __forceinline__ void split_bf(float x, bf& h, bf& l) {
    h = __float2bfloat16(x);
    l = __float2bfloat16(x - __bfloat162float(h));
}
__device__ __forceinline__ u32 sptr(const void* p) {
    return (u32)__cvta_generic_to_shared(p);
}
__device__ __forceinline__ void ldsm4(u32* r, u32 a) {
    asm volatile("ldmatrix.sync.aligned.m8n8.x4.shared.b16 {%0,%1,%2,%3}, [%4];"
                 : "=r"(r[0]), "=r"(r[1]), "=r"(r[2]), "=r"(r[3]) : "r"(a));
}
__device__ __forceinline__ void mma16816(float* d, const u32* a, const u32* b) {
    asm volatile(
        "mma.sync.aligned.m16n8k16.row.col.f32.bf16.bf16.f32 "
        "{%0,%1,%2,%3},{%4,%5,%6,%7},{%8,%9},{%0,%1,%2,%3};"
        : "+f"(d[0]), "+f"(d[1]), "+f"(d[2]), "+f"(d[3])
        : "r"(a[0]), "r"(a[1]), "r"(a[2]), "r"(a[3]), "r"(b[0]), "r"(b[1]));
}
__device__ __forceinline__ void cpa(u32 dst, const void* src, int sz) {
    asm volatile("cp.async.cg.shared.global [%0], [%1], 16, %2;"
                 :: "r"(dst), "l"(src), "r"(sz));
}
__device__ __forceinline__ void cp_commit() {
    asm volatile("cp.async.commit_group;" ::: "memory");
}
__device__ __forceinline__ void cp_wait2() {
    asm volatile("cp.async.wait_group 2;" ::: "memory");
}
#define HBAR(id) asm volatile("bar.sync %0, 256;" :: "r"(id) : "memory")

// ---------------- launch-reentrant grid barrier ----------------
__device__ __forceinline__ void gsync(int nb) {
    __syncthreads();
    if (threadIdx.x == 0) {
        __threadfence();
        unsigned int gen = *(volatile unsigned int*)&g_bar_gen;
        if (atomicAdd(&g_bar_count, 1u) == (unsigned int)(nb - 1)) {
            g_bar_count = 0;
            __threadfence();
            atomicAdd(&g_bar_gen, 1u);
        } else {
            while (*(volatile unsigned int*)&g_bar_gen == gen) { }
        }
        __threadfence();
    }
    __syncthreads();
}

// ---------------- 32-K stage compute: 4 independent accumulator chains ------
__device__ __forceinline__ void stage_mma(bf* buf, int wm, int wn, int lane,
                                          float acc[2][4], float accc[2][4]) {
#pragma unroll
    for (int q = 0; q < 2; q++) {
        u32 ah[4], al[4], bh[4], bl[4];
        u32 abase = sptr(buf + (wm * 16 + (lane & 15)) * PIT
                             + q * 16 + ((lane >> 4) & 1) * 8);
        ldsm4(ah, abase);
        ldsm4(al, abase + MATSZ * 2);
        u32 bbase = sptr(buf + 2 * MATSZ
                             + (wn * 16 + (lane & 7) + ((lane >> 4) & 1) * 8) * PIT
                             + q * 16 + ((lane >> 3) & 1) * 8);
        ldsm4(bh, bbase);
        ldsm4(bl, bbase + MATSZ * 2);
        // main products: chains acc[0], acc[1] (depth 1 per q)
        mma16816(acc[0], ah, bh + 0);
        mma16816(acc[1], ah, bh + 2);
        // correction products: chains accc[0], accc[1] (depth 2 per q)
        mma16816(accc[0], ah, bl + 0);
        mma16816(accc[1], ah, bl + 2);
        mma16816(accc[0], al, bh + 0);
        mma16816(accc[1], al, bh + 2);
    }
}

// ---------------- generic 64x64 mma tile: C = [A1|A2] @ W^T + bias ----------------
__device__ __forceinline__ void mm_tile(
    bf* stg, int tile,
    const bf* __restrict__ A1h, const bf* __restrict__ A1l, int K1,
    const bf* __restrict__ A2h, const bf* __restrict__ A2l, int K2,
    const bf* __restrict__ Wh,  const bf* __restrict__ Wl, int ldw, int N,
    const float* __restrict__ bias, int relu,
    float* __restrict__ Cf, size_t ldc,
    bf* __restrict__ Ch, bf* __restrict__ Cl, int ldcb)
{
    __syncthreads();
    const int tid = threadIdx.x;
    const int lane = tid & 31, warp = tid >> 5;
    const int wm = warp >> 2, wn = warp & 3;
    const int ntN = (N + 63) >> 6;
    const int m0 = (tile / ntN) * 64, n0 = (tile % ntN) * 64;
    const int S = (K1 + K2) >> 5;

    const int smat = tid >> 8;             // 0=hi, 1=lo
    const int srow = (tid >> 2) & 63;
    const int schk = tid & 3;              // 16B chunk in 32-col row
    const int wrow = n0 + srow;
    const int wsz  = (wrow < N) ? 16 : 0;
    const int wr_c = (wrow < N) ? wrow : 0;   // clamped source row

    float acc[2][4] = {};
    float accc[2][4] = {};

    auto issue = [&](int s) {
        int kb = s << 5;
        const bf* Ap; int lda, ka;
        if (kb < K1) { Ap = smat ? A1l : A1h; lda = K1; ka = kb; }
        else         { Ap = smat ? A2l : A2h; lda = K2; ka = kb - K1; }
        bf* buf = stg + (s & 3) * BUFE;
        u32 da = sptr(buf + smat * MATSZ + srow * PIT + schk * 8);
        u32 dw = sptr(buf + (2 + smat) * MATSZ + srow * PIT + schk * 8);
        cpa(da, Ap + (size_t)(m0 + srow) * lda + ka + schk * 8, 16);
        const bf* Wp = smat ? Wl : Wh;
        cpa(dw, Wp + (size_t)wr_c * ldw + kb + schk * 8, wsz);
    };

    if (0 < S) issue(0);
    cp_commit();
    if (1 < S) issue(1);
    cp_commit();
    if (2 < S) issue(2);
    cp_commit();

    for (int s = 0; s < S; s++) {
        cp_wait2();
        __syncthreads();
        if (s + 3 < S) issue(s + 3);
        cp_commit();
        stage_mma(stg + (s & 3) * BUFE, wm, wn, lane, acc, accc);
    }

    // epilogue (register-only + gmem)
#pragma unroll
    for (int bb = 0; bb < 2; bb++) {
        int nc = n0 + wn * 16 + bb * 8 + (lane & 3) * 2;
        int r0 = m0 + wm * 16 + (lane >> 2);
#pragma unroll
        for (int hf = 0; hf < 2; hf++) {
            int r = r0 + hf * 8;
#pragma unroll
            for (int j = 0; j < 2; j++) {
                int n = nc + j;
                if (n < N) {
                    float v = acc[bb][hf * 2 + j] + accc[bb][hf * 2 + j] + bias[n];
                    if (relu) v = fmaxf(v, 0.f);
                    if (Cf) Cf[(size_t)r * ldc + n] = v;
                    if (Ch) {
                        bf vh, vl; split_bf(v, vh, vl);
                        Ch[(size_t)r * ldcb + n] = vh;
                        Cl[(size_t)r * ldcb + n] = vl;
                    }
                }
            }
        }
    }
}

// ---------------- LSTM 64x64 mma tile: gate remap + fused pointwise ----------
__device__ __forceinline__ void lstm_mma(
    bf* stg, int tile,
    const bf* __restrict__ xh, const bf* __restrict__ xl,
    const bf* __restrict__ hhx, const bf* __restrict__ hlx,
    const bf* __restrict__ Wihh, const bf* __restrict__ Wihl,
    const bf* __restrict__ Whhh, const bf* __restrict__ Whhl,
    const float* __restrict__ bih, const float* __restrict__ bhh,
    float* __restrict__ houtf, bf* __restrict__ houth, bf* __restrict__ houtl,
    float* __restrict__ cbuf)
{
    __syncthreads();
    const int tid = threadIdx.x;
    const int lane = tid & 31, warp = tid >> 5;
    const int wm = warp >> 2, wn = warp & 3;
    const int m0 = (tile >> 5) * 64;
    const int d0 = (tile & 31) * 16;

    const int smat = tid >> 8;
    const int srow = (tid >> 2) & 63;
    const int schk = tid & 3;
    const int wrow = ((srow >> 4) << 9) + d0 + (srow & 15);   // gate*512 + d

    float acc[2][4] = {};
    float accc[2][4] = {};

    auto issue = [&](int s) {
        const bf* Ap = (s < 16) ? (smat ? xl : xh) : (smat ? hlx : hhx);
        const bf* Wp = (s < 16) ? (smat ? Wihl : Wihh) : (smat ? Whhl : Whhh);
        int kb = (s & 15) * 32;
        bf* buf = stg + (s & 3) * BUFE;
        u32 da = sptr(buf + smat * MATSZ + srow * PIT + schk * 8);
        u32 dw = sptr(buf + (2 + smat) * MATSZ + srow * PIT + schk * 8);
        cpa(da, Ap + (size_t)(m0 + srow) * 512 + kb + schk * 8, 16);
        cpa(dw, Wp + (size_t)wrow * 512 + kb + schk * 8, 16);
    };

    issue(0); cp_commit();
    issue(1); cp_commit();
    issue(2); cp_commit();

    for (int s = 0; s < 32; s++) {
        cp_wait2();
        __syncthreads();
        if (s + 3 < 32) issue(s + 3);
        cp_commit();
        stage_mma(stg + (s & 3) * BUFE, wm, wn, lane, acc, accc);
    }

    // dump combined frags to smem G[64][68] (slot 0; last compute read slot 3)
    float* G = (float*)stg;
#pragma unroll
    for (int bb = 0; bb < 2; bb++) {
        int c = wn * 16 + bb * 8 + (lane & 3) * 2;
        int r0 = wm * 16 + (lane >> 2);
        *(float2*)(G + r0 * 68 + c)       = make_float2(acc[bb][0] + accc[bb][0],
                                                        acc[bb][1] + accc[bb][1]);
        *(float2*)(G + (r0 + 8) * 68 + c) = make_float2(acc[bb][2] + accc[bb][2],
                                                        acc[bb][3] + accc[bb][3]);
    }
    __syncthreads();

    for (int e = tid; e < 1024; e += NT) {
        int m = e & 63, dp = e >> 6;
        int d = d0 + dp;
        const float* Gm = G + m * 68;
        float gi = Gm[dp]      + bih[d]        + bhh[d];
        float gf = Gm[16 + dp] + bih[512 + d]  + bhh[512 + d];
        float gg = Gm[32 + dp] + bih[1024 + d] + bhh[1024 + d];
        float go = Gm[48 + dp] + bih[1536 + d] + bhh[1536 + d];
        size_t idx = (size_t)(m0 + m) * 512 + d;
        float si = 1.f / (1.f + expf(-gi));
        float sf = 1.f / (1.f + expf(-gf));
        float so = 1.f / (1.f + expf(-go));
        float cn = sf * cbuf[idx] + si * tanhf(gg);
        cbuf[idx] = cn;
        float hn = so * tanhf(cn);
        houtf[idx] = hn;
        bf vh, vl; split_bf(hn, vh, vl);
        houth[idx] = vh;
        houtl[idx] = vl;
    }
}

// ---------------- kernel params ----------------
struct Params {
    const int* act;
    const float* enc;
    const float* enc_h;
    const float* enc_c;
    const float* embW;
    const float* Wc;  const float* bc;
    const float* Wih[3]; const float* Whh[3];
    const float* bih[3]; const float* bhh[3];
    const float* Wa1; const float* ba1;
    const float* Wa2; const float* ba2;
    const float* Wl1; const float* bl1;
    const float* Wl2; const float* bl2;
    float* out;
};

// ---------------- persistent mega-kernel ----------------
__global__ void __launch_bounds__(NT, 1) decoder_kernel(Params p)
{
    extern __shared__ __align__(16) bf stg[];
    const int nb  = gridDim.x;
    const int bid = blockIdx.x;
    const int tid = threadIdx.x;
    const int gt = bid * NT + tid, gs = nb * NT;

    // ---- phase 0: setup ----
    for (int idx = gt; idx < BB * DD; idx += gs) {
        float h = p.enc_h[idx], c = p.enc_c[idx];
        bf vh, vl; split_bf(h, vh, vl);
#pragma unroll
        for (int cc = 0; cc < 3; cc++) {
            g_hf[cc][0][idx] = h;
            g_hh[cc][0][idx] = vh; g_hl[cc][0][idx] = vl;
            g_c[cc][idx] = c;
        }
        g_ctx_h[idx] = __float2bfloat16(0.f);
        g_ctx_l[idx] = __float2bfloat16(0.f);
    }
    for (int i4 = gt; i4 < TT * BB * EMBW / 4; i4 += gs) {
        int row = i4 >> 5;
        int kq  = i4 & 31;
        int t = row >> 8;
        int b = row & 255;
        float4 v = make_float4(0.f, 0.f, 0.f, 0.f);
        if (t > 0) {
            int a = p.act[b * TT + t - 1];
            v = *(const float4*)(p.embW + (size_t)a * EMBW + kq * 4);
        }
        size_t base = (size_t)row * EMBW + kq * 4;
        bf vh, vl;
        split_bf(v.x, vh, vl); g_eseq_h[base + 0] = vh; g_eseq_l[base + 0] = vl;
        split_bf(v.y, vh, vl); g_eseq_h[base + 1] = vh; g_eseq_l[base + 1] = vl;
        split_bf(v.z, vh, vl); g_eseq_h[base + 2] = vh; g_eseq_l[base + 2] = vl;
        split_bf(v.w, vh, vl); g_eseq_h[base + 3] = vh; g_eseq_l[base + 3] = vl;
    }
    for (int i = gt; i < DD * (EMBW + EENC); i += gs) {
        bf vh, vl; split_bf(p.Wc[i], vh, vl);
        g_Wc_h[i] = vh; g_Wc_l[i] = vl;
    }
#pragma unroll
    for (int cc = 0; cc < 3; cc++) {
        for (int i = gt; i < 4 * DD * DD; i += gs) {
            bf vh, vl;
            split_bf(p.Wih[cc][i], vh, vl); g_Wih_h[cc][i] = vh; g_Wih_l[cc][i] = vl;
            split_bf(p.Whh[cc][i], vh, vl); g_Whh_h[cc][i] = vh; g_Whh_l[cc][i] = vl;
        }
    }
    for (int i = gt; i < DD * (DD + EENC); i += gs) {
        bf vh, vl; split_bf(p.Wl1[i], vh, vl);
        g_Wl1_h[i] = vh; g_Wl1_l[i] = vl;
    }
    for (int i = gt; i < AA * DD; i += gs) {
        bf vh, vl; split_bf(p.Wl2[i], vh, vl);
        g_Wl2_h[i] = vh; g_Wl2_l[i] = vl;
    }
    {
        int lane = tid & 31;
        int gw0 = gt >> 5;
        for (int gw = gw0; gw < BB * LL; gw += gs >> 5) {
            const float* er = p.enc + (size_t)gw * EENC;
            float r[16];
#pragma unroll
            for (int i = 0; i < 16; i++) r[i] = er[lane + 32 * i];
            for (int j = 0; j < ATTH; j++) {
                const float* w = p.Wa1 + (size_t)j * (EENC + DD);
                float s = 0.f;
#pragma unroll
                for (int i = 0; i < 16; i++) s += r[i] * w[lane + 32 * i];
#pragma unroll
                for (int o = 16; o; o >>= 1) s += __shfl_xor_sync(0xFFFFFFFFu, s, o);
                if (lane == 0) g_encatt[(size_t)gw * ATTH + j] = s + p.ba1[j];
            }
        }
    }
    gsync(nb);

    // ---- att for t=0 ----
    for (int u = bid; u < 32; u += nb)
        mm_tile(stg, u, g_eseq_h, g_eseq_l, EMBW, g_ctx_h, g_ctx_l, EENC,
                g_Wc_h, g_Wc_l, EMBW + EENC, DD, p.bc, 0,
                (float*)0, 0, g_att_h, g_att_l, DD);
    gsync(nb);

    // ---- main loop ----
    for (int t = 0; t < TT; t++) {
        const int cur = t & 1, nxt = cur ^ 1;

        // Phase A: LSTM cell0 (+ logits of t-1, independent)
        {
            const int ntA = 128 + (t > 0 ? 12 : 0);
            for (int u = bid; u < ntA; u += nb) {
                if (u < 128)
                    lstm_mma(stg, u, g_att_h, g_att_l,
                             g_hh[0][cur], g_hl[0][cur],
                             g_Wih_h[0], g_Wih_l[0], g_Whh_h[0], g_Whh_l[0],
                             p.bih[0], p.bhh[0],
                             g_hf[0][nxt], g_hh[0][nxt], g_hl[0][nxt], g_c[0]);
                else
                    mm_tile(stg, u - 128, g_act1_h, g_act1_l, DD,
                            (const bf*)0, (const bf*)0, 0,
                            g_Wl2_h, g_Wl2_l, DD, AA, p.bl2, 0,
                            p.out + (size_t)(t - 1) * AA, (size_t)TT * AA,
                            (bf*)0, (bf*)0, 0);
            }
            gsync(nb);
        }

        // Phases B, C: cells 1, 2
        for (int cell = 1; cell < 3; cell++) {
            for (int u = bid; u < 128; u += nb)
                lstm_mma(stg, u, g_hh[cell - 1][nxt], g_hl[cell - 1][nxt],
                         g_hh[cell][cur], g_hl[cell][cur],
                         g_Wih_h[cell], g_Wih_l[cell],
                         g_Whh_h[cell], g_Whh_l[cell],
                         p.bih[cell], p.bhh[cell],
                         g_hf[cell][nxt], g_hh[cell][nxt], g_hl[cell][nxt],
                         g_c[cell]);
            gsync(nb);
        }

        // Phase D: attention, 2 rows/block via half-block barriers
        __syncthreads();
        {
            const int half = tid >> 8;
            const int htid = tid & 255;
            const int barid = 1 + half;
            float* smf = (float*)stg + half * 2048;
            const int warp8 = htid >> 5, lane = htid & 31;
            for (int b = bid * 2 + half; b < BB; b += nb * 2) {
                float* sh_h  = smf;
                float* sh_hp = smf + 512;
                float* sh_s  = smf + 544;
                const float* h2 = g_hf[2][nxt];
                for (int k = htid; k < DD; k += 256) sh_h[k] = h2[(size_t)b * DD + k];
                HBAR(barid);
                for (int j = warp8; j < ATTH; j += 8) {
                    const float* w = p.Wa1 + (size_t)j * (EENC + DD) + EENC;
                    float s = 0.f;
                    for (int k = lane; k < DD; k += 32) s += sh_h[k] * w[k];
#pragma unroll
                    for (int o = 16; o; o >>= 1) s += __shfl_xor_sync(0xFFFFFFFFu, s, o);
                    if (lane == 0) sh_hp[j] = s;
                }
                HBAR(barid);
                if (htid < LL) {
                    const float* ea = g_encatt + ((size_t)b * LL + htid) * ATTH;
                    float s = 0.f;
#pragma unroll
                    for (int j = 0; j < ATTH; j++) {
                        float v = ea[j] + sh_hp[j];
                        v = v > 0.f ? v : 0.f;
                        s += v * p.Wa2[j];
                    }
                    sh_s[htid] = tanhf(s + p.ba2[0]);
                }
                HBAR(barid);
                if (warp8 == 0) {
                    float v0 = sh_s[lane], v1 = sh_s[lane + 32];
                    float m = fmaxf(v0, v1);
#pragma unroll
                    for (int o = 16; o; o >>= 1) m = fmaxf(m, __shfl_xor_sync(0xFFFFFFFFu, m, o));
                    float e0 = expf(v0 - m), e1 = expf(v1 - m);
                    float sum = e0 + e1;
#pragma unroll
                    for (int o = 16; o; o >>= 1) sum += __shfl_xor_sync(0xFFFFFFFFu, sum, o);
                    float inv = 1.f / sum;
                    sh_s[lane] = e0 * inv;
                    sh_s[lane + 32] = e1 * inv;
                }
                HBAR(barid);
                const float* eb = p.enc + (size_t)b * LL * EENC;
                for (int k = htid; k < EENC; k += 256) {
                    float s = 0.f;
#pragma unroll 8
                    for (int l = 0; l < LL; l++) s += sh_s[l] * eb[(size_t)l * EENC + k];
                    bf vh, vl; split_bf(s, vh, vl);
                    g_ctx_h[(size_t)b * EENC + k] = vh;
                    g_ctx_l[(size_t)b * EENC + k] = vl;
                }
            }
        }
        gsync(nb);

        // Phase E: Wl1 + att(t+1) — independent given ctx
        {
            const int ntE = 32 + ((t + 1 < TT) ? 32 : 0);
            for (int u = bid; u < ntE; u += nb) {
                if (u < 32)
                    mm_tile(stg, u, g_hh[2][nxt], g_hl[2][nxt], DD,
                            g_ctx_h, g_ctx_l, EENC,
                            g_Wl1_h, g_Wl1_l, DD + EENC, DD, p.bl1, 1,
                            (float*)0, 0, g_act1_h, g_act1_l, DD);
                else
                    mm_tile(stg, u - 32,
                            g_eseq_h + (size_t)(t + 1) * BB * EMBW,
                            g_eseq_l + (size_t)(t + 1) * BB * EMBW, EMBW,
                            g_ctx_h, g_ctx_l, EENC,
                            g_Wc_h, g_Wc_l, EMBW + EENC, DD, p.bc, 0,
                            (float*)0, 0, g_att_h, g_att_l, DD);
            }
            gsync(nb);
        }
    }

    // final logits (t = TT-1)
    for (int u = bid; u < 12; u += nb)
        mm_tile(stg, u, g_act1_h, g_act1_l, DD, (const bf*)0, (const bf*)0, 0,
                g_Wl2_h, g_Wl2_l, DD, AA, p.bl2, 0,
                p.out + (size_t)(TT - 1) * AA, (size_t)TT * AA,
                (bf*)0, (bf*)0, 0);
}

// ---------------- host ----------------
extern "C" void kernel_launch(void* const* d_in, const int* in_sizes, int n_in,
                              void* d_out, int out_size)
{
    Params p;
    p.act    = (const int*)  d_in[0];
    p.enc    = (const float*)d_in[1];
    p.enc_h  = (const float*)d_in[2];
    p.enc_c  = (const float*)d_in[3];
    p.embW   = (const float*)d_in[4];
    p.Wc     = (const float*)d_in[5];
    p.bc     = (const float*)d_in[6];
    p.Wih[0] = (const float*)d_in[7];  p.Whh[0] = (const float*)d_in[8];
    p.bih[0] = (const float*)d_in[9];  p.bhh[0] = (const float*)d_in[10];
    p.Wih[1] = (const float*)d_in[11]; p.Whh[1] = (const float*)d_in[12];
    p.bih[1] = (const float*)d_in[13]; p.bhh[1] = (const float*)d_in[14];
    p.Wih[2] = (const float*)d_in[15]; p.Whh[2] = (const float*)d_in[16];
    p.bih[2] = (const float*)d_in[17]; p.bhh[2] = (const float*)d_in[18];
    p.Wa1 = (const float*)d_in[19]; p.ba1 = (const float*)d_in[20];
    p.Wa2 = (const float*)d_in[21]; p.ba2 = (const float*)d_in[22];
    p.Wl1 = (const float*)d_in[23]; p.bl1 = (const float*)d_in[24];
    p.Wl2 = (const float*)d_in[25]; p.bl2 = (const float*)d_in[26];
    p.out = (float*)d_out;

    int dev = 0;
    cudaGetDevice(&dev);
    int nsm = 0;
    cudaDeviceGetAttribute(&nsm, cudaDevAttrMultiProcessorCount, dev);
    if (nsm <= 0) nsm = 148;

    cudaFuncSetAttribute(decoder_kernel,
                         cudaFuncAttributeMaxDynamicSharedMemorySize, SMEM_BYTES);
    decoder_kernel<<<nsm, NT, SMEM_BYTES>>>(p);
}

// round 10
// speedup vs baseline: 1.1026x; 1.0028x over previous
#include <cuda_runtime.h>
#include <cuda_bf16.h>
#include <math.h>

#define BB   256
#define TT   128
#define LL   64
#define EENC 512
#define DD   512
#define EMBW 128
#define AA   129
#define ATTH 20

#define NT   512

#define PIT    40                  // smem row pitch in bf16 (80B, ldsm conflict-free)
#define MATSZ  (64 * PIT)          // one 64x32 staged matrix (2560 elems)
#define BUFE   (4 * MATSZ)         // Ahi, Alo, Whi, Wlo per stage (10240 elems)
#define RING   4
#define SMEM_BYTES (RING * BUFE * 2)   // 81920 B

typedef unsigned int u32;
typedef __nv_bfloat16 bf;

// ---------------- device scratch (static, no allocs) ----------------
__device__ __align__(16) bf    g_eseq_h[TT * BB * EMBW];
__device__ __align__(16) bf    g_eseq_l[TT * BB * EMBW];
__device__ __align__(16) float g_encatt[BB * LL * ATTH];
__device__ __align__(16) bf    g_att_h[BB * DD],  g_att_l[BB * DD];
__device__ __align__(16) float g_hf[3][2][BB * DD];
__device__ __align__(16) bf    g_hh[3][2][BB * DD], g_hl[3][2][BB * DD];
__device__ __align__(16) float g_c[3][BB * DD];
__device__ __align__(16) bf    g_ctx_h[BB * EENC], g_ctx_l[BB * EENC];
__device__ __align__(16) bf    g_act1_h[BB * DD],  g_act1_l[BB * DD];

__device__ __align__(16) bf g_Wc_h[DD * (EMBW + EENC)],  g_Wc_l[DD * (EMBW + EENC)];
__device__ __align__(16) bf g_Wih_h[3][4 * DD * DD], g_Wih_l[3][4 * DD * DD];
__device__ __align__(16) bf g_Whh_h[3][4 * DD * DD], g_Whh_l[3][4 * DD * DD];
__device__ __align__(16) bf g_Wl1_h[DD * (DD + EENC)], g_Wl1_l[DD * (DD + EENC)];
__device__ __align__(16) bf g_Wl2_h[AA * DD], g_Wl2_l[AA * DD];

__device__ unsigned int g_bar_count = 0;
__device__ unsigned int g_bar_gen   = 0;

// ---------------- helpers ----------------
__device__ __forceinline__ void split_bf(float x, bf& h, bf& l) {
    h = __float2bfloat16(x);
    l = __float2bfloat16(x - __bfloat162float(h));
}
__device__ __forceinline__ u32 sptr(const void* p) {
    return (u32)__cvta_generic_to_shared(p);
}
__device__ __forceinline__ void ldsm4(u32* r, u32 a) {
    asm volatile("ldmatrix.sync.aligned.m8n8.x4.shared.b16 {%0,%1,%2,%3}, [%4];"
                 : "=r"(r[0]), "=r"(r[1]), "=r"(r[2]), "=r"(r[3]) : "r"(a));
}
__device__ __forceinline__ void mma16816(float* d, const u32* a, const u32* b) {
    asm volatile(
        "mma.sync.aligned.m16n8k16.row.col.f32.bf16.bf16.f32 "
        "{%0,%1,%2,%3},{%4,%5,%6,%7},{%8,%9},{%0,%1,%2,%3};"
        : "+f"(d[0]), "+f"(d[1]), "+f"(d[2]), "+f"(d[3])
        : "r"(a[0]), "r"(a[1]), "r"(a[2]), "r"(a[3]), "r"(b[0]), "r"(b[1]));
}
__device__ __forceinline__ void cpa(u32 dst, const void* src, int sz) {
    asm volatile("cp.async.cg.shared.global [%0], [%1], 16, %2;"
                 :: "r"(dst), "l"(src), "r"(sz));
}
__device__ __forceinline__ void cp_commit() {
    asm volatile("cp.async.commit_group;" ::: "memory");
}
__device__ __forceinline__ void cp_wait2() {
    asm volatile("cp.async.wait_group 2;" ::: "memory");
}
#define HBAR(id) asm volatile("bar.sync %0, 256;" :: "r"(id) : "memory")

// ---------------- launch-reentrant grid barrier ----------------
__device__ __forceinline__ void gsync(int nb) {
    __syncthreads();
    if (threadIdx.x == 0) {
        __threadfence();
        unsigned int gen = *(volatile unsigned int*)&g_bar_gen;
        if (atomicAdd(&g_bar_count, 1u) == (unsigned int)(nb - 1)) {
            g_bar_count = 0;
            __threadfence();
            atomicAdd(&g_bar_gen, 1u);
        } else {
            while (*(volatile unsigned int*)&g_bar_gen == gen) { }
        }
        __threadfence();
    }
    __syncthreads();
}

// ---------------- 32-K stage compute: 4 independent accumulator chains ------
__device__ __forceinline__ void stage_mma(bf* buf, int wm, int wn, int lane,
                                          float acc[2][4], float accc[2][4]) {
#pragma unroll
    for (int q = 0; q < 2; q++) {
        u32 ah[4], al[4], bh[4], bl[4];
        u32 abase = sptr(buf + (wm * 16 + (lane & 15)) * PIT
                             + q * 16 + ((lane >> 4) & 1) * 8);
        ldsm4(ah, abase);
        ldsm4(al, abase + MATSZ * 2);
        u32 bbase = sptr(buf + 2 * MATSZ
                             + (wn * 16 + (lane & 7) + ((lane >> 4) & 1) * 8) * PIT
                             + q * 16 + ((lane >> 3) & 1) * 8);
        ldsm4(bh, bbase);
        ldsm4(bl, bbase + MATSZ * 2);
        // main products: chains acc[0], acc[1] (depth 1 per q)
        mma16816(acc[0], ah, bh + 0);
        mma16816(acc[1], ah, bh + 2);
        // correction products: chains accc[0], accc[1] (depth 2 per q)
        mma16816(accc[0], ah, bl + 0);
        mma16816(accc[1], ah, bl + 2);
        mma16816(accc[0], al, bh + 0);
        mma16816(accc[1], al, bh + 2);
    }
}

// ---------------- generic 64x64 mma tile: C = [A1|A2] @ W^T + bias ----------------
__device__ __forceinline__ void mm_tile(
    bf* stg, int tile,
    const bf* __restrict__ A1h, const bf* __restrict__ A1l, int K1,
    const bf* __restrict__ A2h, const bf* __restrict__ A2l, int K2,
    const bf* __restrict__ Wh,  const bf* __restrict__ Wl, int ldw, int N,
    const float* __restrict__ bias, int relu,
    float* __restrict__ Cf, size_t ldc,
    bf* __restrict__ Ch, bf* __restrict__ Cl, int ldcb)
{
    __syncthreads();
    const int tid = threadIdx.x;
    const int lane = tid & 31, warp = tid >> 5;
    const int wm = warp >> 2, wn = warp & 3;
    const int ntN = (N + 63) >> 6;
    const int m0 = (tile / ntN) * 64, n0 = (tile % ntN) * 64;
    const int S = (K1 + K2) >> 5;

    const int smat = tid >> 8;             // 0=hi, 1=lo
    const int srow = (tid >> 2) & 63;
    const int schk = tid & 3;              // 16B chunk in 32-col row
    const int wrow = n0 + srow;
    const int wsz  = (wrow < N) ? 16 : 0;
    const int wr_c = (wrow < N) ? wrow : 0;   // clamped source row

    float acc[2][4] = {};
    float accc[2][4] = {};

    auto issue = [&](int s) {
        int kb = s << 5;
        const bf* Ap; int lda, ka;
        if (kb < K1) { Ap = smat ? A1l : A1h; lda = K1; ka = kb; }
        else         { Ap = smat ? A2l : A2h; lda = K2; ka = kb - K1; }
        bf* buf = stg + (s & 3) * BUFE;
        u32 da = sptr(buf + smat * MATSZ + srow * PIT + schk * 8);
        u32 dw = sptr(buf + (2 + smat) * MATSZ + srow * PIT + schk * 8);
        cpa(da, Ap + (size_t)(m0 + srow) * lda + ka + schk * 8, 16);
        const bf* Wp = smat ? Wl : Wh;
        cpa(dw, Wp + (size_t)wr_c * ldw + kb + schk * 8, wsz);
    };

    if (0 < S) issue(0);
    cp_commit();
    if (1 < S) issue(1);
    cp_commit();
    if (2 < S) issue(2);
    cp_commit();

    for (int s = 0; s < S; s++) {
        cp_wait2();
        __syncthreads();
        if (s + 3 < S) issue(s + 3);
        cp_commit();
        stage_mma(stg + (s & 3) * BUFE, wm, wn, lane, acc, accc);
    }

    // epilogue (register-only + gmem)
#pragma unroll
    for (int bb = 0; bb < 2; bb++) {
        int nc = n0 + wn * 16 + bb * 8 + (lane & 3) * 2;
        int r0 = m0 + wm * 16 + (lane >> 2);
#pragma unroll
        for (int hf = 0; hf < 2; hf++) {
            int r = r0 + hf * 8;
#pragma unroll
            for (int j = 0; j < 2; j++) {
                int n = nc + j;
                if (n < N) {
                    float v = acc[bb][hf * 2 + j] + accc[bb][hf * 2 + j] + bias[n];
                    if (relu) v = fmaxf(v, 0.f);
                    if (Cf) Cf[(size_t)r * ldc + n] = v;
                    if (Ch) {
                        bf vh, vl; split_bf(v, vh, vl);
                        Ch[(size_t)r * ldcb + n] = vh;
                        Cl[(size_t)r * ldcb + n] = vl;
                    }
                }
            }
        }
    }
}

// ---------------- LSTM 64x64 mma tile: gate remap + fused pointwise ----------
__device__ __forceinline__ void lstm_mma(
    bf* stg, int tile,
    const bf* __restrict__ xh, const bf* __restrict__ xl,
    const bf* __restrict__ hhx, const bf* __restrict__ hlx,
    const bf* __restrict__ Wihh, const bf* __restrict__ Wihl,
    const bf* __restrict__ Whhh, const bf* __restrict__ Whhl,
    const float* __restrict__ bih, const float* __restrict__ bhh,
    float* __restrict__ houtf, bf* __restrict__ houth, bf* __restrict__ houtl,
    float* __restrict__ cbuf)
{
    __syncthreads();
    const int tid = threadIdx.x;
    const int lane = tid & 31, warp = tid >> 5;
    const int wm = warp >> 2, wn = warp & 3;
    const int m0 = (tile >> 5) * 64;
    const int d0 = (tile & 31) * 16;

    const int smat = tid >> 8;
    const int srow = (tid >> 2) & 63;
    const int schk = tid & 3;
    const int wrow = ((srow >> 4) << 9) + d0 + (srow & 15);   // gate*512 + d

    float acc[2][4] = {};
    float accc[2][4] = {};

    auto issue = [&](int s) {
        const bf* Ap = (s < 16) ? (smat ? xl : xh) : (smat ? hlx : hhx);
        const bf* Wp = (s < 16) ? (smat ? Wihl : Wihh) : (smat ? Whhl : Whhh);
        int kb = (s & 15) * 32;
        bf* buf = stg + (s & 3) * BUFE;
        u32 da = sptr(buf + smat * MATSZ + srow * PIT + schk * 8);
        u32 dw = sptr(buf + (2 + smat) * MATSZ + srow * PIT + schk * 8);
        cpa(da, Ap + (size_t)(m0 + srow) * 512 + kb + schk * 8, 16);
        cpa(dw, Wp + (size_t)wrow * 512 + kb + schk * 8, 16);
    };

    issue(0); cp_commit();
    issue(1); cp_commit();
    issue(2); cp_commit();

    for (int s = 0; s < 32; s++) {
        cp_wait2();
        __syncthreads();
        if (s + 3 < 32) issue(s + 3);
        cp_commit();
        stage_mma(stg + (s & 3) * BUFE, wm, wn, lane, acc, accc);
    }

    // dump combined frags to smem G[64][68] (slot 0; last compute read slot 3)
    float* G = (float*)stg;
#pragma unroll
    for (int bb = 0; bb < 2; bb++) {
        int c = wn * 16 + bb * 8 + (lane & 3) * 2;
        int r0 = wm * 16 + (lane >> 2);
        *(float2*)(G + r0 * 68 + c)       = make_float2(acc[bb][0] + accc[bb][0],
                                                        acc[bb][1] + accc[bb][1]);
        *(float2*)(G + (r0 + 8) * 68 + c) = make_float2(acc[bb][2] + accc[bb][2],
                                                        acc[bb][3] + accc[bb][3]);
    }
    __syncthreads();

    for (int e = tid; e < 1024; e += NT) {
        int m = e & 63, dp = e >> 6;
        int d = d0 + dp;
        const float* Gm = G + m * 68;
        float gi = Gm[dp]      + bih[d]        + bhh[d];
        float gf = Gm[16 + dp] + bih[512 + d]  + bhh[512 + d];
        float gg = Gm[32 + dp] + bih[1024 + d] + bhh[1024 + d];
        float go = Gm[48 + dp] + bih[1536 + d] + bhh[1536 + d];
        size_t idx = (size_t)(m0 + m) * 512 + d;
        float si = 1.f / (1.f + expf(-gi));
        float sf = 1.f / (1.f + expf(-gf));
        float so = 1.f / (1.f + expf(-go));
        float cn = sf * cbuf[idx] + si * tanhf(gg);
        cbuf[idx] = cn;
        float hn = so * tanhf(cn);
        houtf[idx] = hn;
        bf vh, vl; split_bf(hn, vh, vl);
        houth[idx] = vh;
        houtl[idx] = vl;
    }
}

// ---------------- kernel params ----------------
struct Params {
    const int* act;
    const float* enc;
    const float* enc_h;
    const float* enc_c;
    const float* embW;
    const float* Wc;  const float* bc;
    const float* Wih[3]; const float* Whh[3];
    const float* bih[3]; const float* bhh[3];
    const float* Wa1; const float* ba1;
    const float* Wa2; const float* ba2;
    const float* Wl1; const float* bl1;
    const float* Wl2; const float* bl2;
    float* out;
};

// ---------------- persistent mega-kernel ----------------
__global__ void __launch_bounds__(NT, 1) decoder_kernel(Params p)
{
    extern __shared__ __align__(16) bf stg[];
    const int nb  = gridDim.x;
    const int bid = blockIdx.x;
    const int tid = threadIdx.x;
    const int gt = bid * NT + tid, gs = nb * NT;

    // ---- phase 0: setup ----
    for (int idx = gt; idx < BB * DD; idx += gs) {
        float h = p.enc_h[idx], c = p.enc_c[idx];
        bf vh, vl; split_bf(h, vh, vl);
#pragma unroll
        for (int cc = 0; cc < 3; cc++) {
            g_hf[cc][0][idx] = h;
            g_hh[cc][0][idx] = vh; g_hl[cc][0][idx] = vl;
            g_c[cc][idx] = c;
        }
        g_ctx_h[idx] = __float2bfloat16(0.f);
        g_ctx_l[idx] = __float2bfloat16(0.f);
    }
    for (int i4 = gt; i4 < TT * BB * EMBW / 4; i4 += gs) {
        int row = i4 >> 5;
        int kq  = i4 & 31;
        int t = row >> 8;
        int b = row & 255;
        float4 v = make_float4(0.f, 0.f, 0.f, 0.f);
        if (t > 0) {
            int a = p.act[b * TT + t - 1];
            v = *(const float4*)(p.embW + (size_t)a * EMBW + kq * 4);
        }
        size_t base = (size_t)row * EMBW + kq * 4;
        bf vh, vl;
        split_bf(v.x, vh, vl); g_eseq_h[base + 0] = vh; g_eseq_l[base + 0] = vl;
        split_bf(v.y, vh, vl); g_eseq_h[base + 1] = vh; g_eseq_l[base + 1] = vl;
        split_bf(v.z, vh, vl); g_eseq_h[base + 2] = vh; g_eseq_l[base + 2] = vl;
        split_bf(v.w, vh, vl); g_eseq_h[base + 3] = vh; g_eseq_l[base + 3] = vl;
    }
    for (int i = gt; i < DD * (EMBW + EENC); i += gs) {
        bf vh, vl; split_bf(p.Wc[i], vh, vl);
        g_Wc_h[i] = vh; g_Wc_l[i] = vl;
    }
#pragma unroll
    for (int cc = 0; cc < 3; cc++) {
        for (int i = gt; i < 4 * DD * DD; i += gs) {
            bf vh, vl;
            split_bf(p.Wih[cc][i], vh, vl); g_Wih_h[cc][i] = vh; g_Wih_l[cc][i] = vl;
            split_bf(p.Whh[cc][i], vh, vl); g_Whh_h[cc][i] = vh; g_Whh_l[cc][i] = vl;
        }
    }
    for (int i = gt; i < DD * (DD + EENC); i += gs) {
        bf vh, vl; split_bf(p.Wl1[i], vh, vl);
        g_Wl1_h[i] = vh; g_Wl1_l[i] = vl;
    }
    for (int i = gt; i < AA * DD; i += gs) {
        bf vh, vl; split_bf(p.Wl2[i], vh, vl);
        g_Wl2_h[i] = vh; g_Wl2_l[i] = vl;
    }
    {
        int lane = tid & 31;
        int gw0 = gt >> 5;
        for (int gw = gw0; gw < BB * LL; gw += gs >> 5) {
            const float* er = p.enc + (size_t)gw * EENC;
            float r[16];
#pragma unroll
            for (int i = 0; i < 16; i++) r[i] = er[lane + 32 * i];
            for (int j = 0; j < ATTH; j++) {
                const float* w = p.Wa1 + (size_t)j * (EENC + DD);
                float s = 0.f;
#pragma unroll
                for (int i = 0; i < 16; i++) s += r[i] * w[lane + 32 * i];
#pragma unroll
                for (int o = 16; o; o >>= 1) s += __shfl_xor_sync(0xFFFFFFFFu, s, o);
                if (lane == 0) g_encatt[(size_t)gw * ATTH + j] = s + p.ba1[j];
            }
        }
    }
    gsync(nb);

    // ---- att for t=0 ----
    for (int u = bid; u < 32; u += nb)
        mm_tile(stg, u, g_eseq_h, g_eseq_l, EMBW, g_ctx_h, g_ctx_l, EENC,
                g_Wc_h, g_Wc_l, EMBW + EENC, DD, p.bc, 0,
                (float*)0, 0, g_att_h, g_att_l, DD);
    gsync(nb);

    // ---- main loop ----
    for (int t = 0; t < TT; t++) {
        const int cur = t & 1, nxt = cur ^ 1;

        // Phase A: LSTM cell0 (+ logits of t-1, independent)
        {
            const int ntA = 128 + (t > 0 ? 12 : 0);
            for (int u = bid; u < ntA; u += nb) {
                if (u < 128)
                    lstm_mma(stg, u, g_att_h, g_att_l,
                             g_hh[0][cur], g_hl[0][cur],
                             g_Wih_h[0], g_Wih_l[0], g_Whh_h[0], g_Whh_l[0],
                             p.bih[0], p.bhh[0],
                             g_hf[0][nxt], g_hh[0][nxt], g_hl[0][nxt], g_c[0]);
                else
                    mm_tile(stg, u - 128, g_act1_h, g_act1_l, DD,
                            (const bf*)0, (const bf*)0, 0,
                            g_Wl2_h, g_Wl2_l, DD, AA, p.bl2, 0,
                            p.out + (size_t)(t - 1) * AA, (size_t)TT * AA,
                            (bf*)0, (bf*)0, 0);
            }
            gsync(nb);
        }

        // Phases B, C: cells 1, 2
        for (int cell = 1; cell < 3; cell++) {
            for (int u = bid; u < 128; u += nb)
                lstm_mma(stg, u, g_hh[cell - 1][nxt], g_hl[cell - 1][nxt],
                         g_hh[cell][cur], g_hl[cell][cur],
                         g_Wih_h[cell], g_Wih_l[cell],
                         g_Whh_h[cell], g_Whh_l[cell],
                         p.bih[cell], p.bhh[cell],
                         g_hf[cell][nxt], g_hh[cell][nxt], g_hl[cell][nxt],
                         g_c[cell]);
            gsync(nb);
        }

        // Phase D: attention, 2 rows/block via half-block barriers
        __syncthreads();
        {
            const int half = tid >> 8;
            const int htid = tid & 255;
            const int barid = 1 + half;
            float* smf = (float*)stg + half * 2048;
            const int warp8 = htid >> 5, lane = htid & 31;
            for (int b = bid * 2 + half; b < BB; b += nb * 2) {
                float* sh_h  = smf;
                float* sh_hp = smf + 512;
                float* sh_s  = smf + 544;
                const float* h2 = g_hf[2][nxt];
                for (int k = htid; k < DD; k += 256) sh_h[k] = h2[(size_t)b * DD + k];
                HBAR(barid);
                for (int j = warp8; j < ATTH; j += 8) {
                    const float* w = p.Wa1 + (size_t)j * (EENC + DD) + EENC;
                    float s = 0.f;
                    for (int k = lane; k < DD; k += 32) s += sh_h[k] * w[k];
#pragma unroll
                    for (int o = 16; o; o >>= 1) s += __shfl_xor_sync(0xFFFFFFFFu, s, o);
                    if (lane == 0) sh_hp[j] = s;
                }
                HBAR(barid);
                if (htid < LL) {
                    const float* ea = g_encatt + ((size_t)b * LL + htid) * ATTH;
                    float s = 0.f;
#pragma unroll
                    for (int j = 0; j < ATTH; j++) {
                        float v = ea[j] + sh_hp[j];
                        v = v > 0.f ? v : 0.f;
                        s += v * p.Wa2[j];
                    }
                    sh_s[htid] = tanhf(s + p.ba2[0]);
                }
                HBAR(barid);
                if (warp8 == 0) {
                    float v0 = sh_s[lane], v1 = sh_s[lane + 32];
                    float m = fmaxf(v0, v1);
#pragma unroll
                    for (int o = 16; o; o >>= 1) m = fmaxf(m, __shfl_xor_sync(0xFFFFFFFFu, m, o));
                    float e0 = expf(v0 - m), e1 = expf(v1 - m);
                    float sum = e0 + e1;
#pragma unroll
                    for (int o = 16; o; o >>= 1) sum += __shfl_xor_sync(0xFFFFFFFFu, sum, o);
                    float inv = 1.f / sum;
                    sh_s[lane] = e0 * inv;
                    sh_s[lane + 32] = e1 * inv;
                }
                HBAR(barid);
                const float* eb = p.enc + (size_t)b * LL * EENC;
                for (int k = htid; k < EENC; k += 256) {
                    float s = 0.f;
#pragma unroll 8
                    for (int l = 0; l < LL; l++) s += sh_s[l] * eb[(size_t)l * EENC + k];
                    bf vh, vl; split_bf(s, vh, vl);
                    g_ctx_h[(size_t)b * EENC + k] = vh;
                    g_ctx_l[(size_t)b * EENC + k] = vl;
                }
            }
        }
        gsync(nb);

        // Phase E: Wl1 + att(t+1) — independent given ctx
        {
            const int ntE = 32 + ((t + 1 < TT) ? 32 : 0);
            for (int u = bid; u < ntE; u += nb) {
                if (u < 32)
                    mm_tile(stg, u, g_hh[2][nxt], g_hl[2][nxt], DD,
                            g_ctx_h, g_ctx_l, EENC,
                            g_Wl1_h, g_Wl1_l, DD + EENC, DD, p.bl1, 1,
                            (float*)0, 0, g_act1_h, g_act1_l, DD);
                else
                    mm_tile(stg, u - 32,
                            g_eseq_h + (size_t)(t + 1) * BB * EMBW,
                            g_eseq_l + (size_t)(t + 1) * BB * EMBW, EMBW,
                            g_ctx_h, g_ctx_l, EENC,
                            g_Wc_h, g_Wc_l, EMBW + EENC, DD, p.bc, 0,
                            (float*)0, 0, g_att_h, g_att_l, DD);
            }
            gsync(nb);
        }
    }

    // final logits (t = TT-1)
    for (int u = bid; u < 12; u += nb)
        mm_tile(stg, u, g_act1_h, g_act1_l, DD, (const bf*)0, (const bf*)0, 0,
                g_Wl2_h, g_Wl2_l, DD, AA, p.bl2, 0,
                p.out + (size_t)(TT - 1) * AA, (size_t)TT * AA,
                (bf*)0, (bf*)0, 0);
}

// ---------------- host ----------------
extern "C" void kernel_launch(void* const* d_in, const int* in_sizes, int n_in,
                              void* d_out, int out_size)
{
    Params p;
    p.act    = (const int*)  d_in[0];
    p.enc    = (const float*)d_in[1];
    p.enc_h  = (const float*)d_in[2];
    p.enc_c  = (const float*)d_in[3];
    p.embW   = (const float*)d_in[4];
    p.Wc     = (const float*)d_in[5];
    p.bc     = (const float*)d_in[6];
    p.Wih[0] = (const float*)d_in[7];  p.Whh[0] = (const float*)d_in[8];
    p.bih[0] = (const float*)d_in[9];  p.bhh[0] = (const float*)d_in[10];
    p.Wih[1] = (const float*)d_in[11]; p.Whh[1] = (const float*)d_in[12];
    p.bih[1] = (const float*)d_in[13]; p.bhh[1] = (const float*)d_in[14];
    p.Wih[2] = (const float*)d_in[15]; p.Whh[2] = (const float*)d_in[16];
    p.bih[2] = (const float*)d_in[17]; p.bhh[2] = (const float*)d_in[18];
    p.Wa1 = (const float*)d_in[19]; p.ba1 = (const float*)d_in[20];
    p.Wa2 = (const float*)d_in[21]; p.ba2 = (const float*)d_in[22];
    p.Wl1 = (const float*)d_in[23]; p.bl1 = (const float*)d_in[24];
    p.Wl2 = (const float*)d_in[25]; p.bl2 = (const float*)d_in[26];
    p.out = (float*)d_out;

    int dev = 0;
    cudaGetDevice(&dev);
    int nsm = 0;
    cudaDeviceGetAttribute(&nsm, cudaDevAttrMultiProcessorCount, dev);
    if (nsm <= 0) nsm = 148;

    cudaFuncSetAttribute(decoder_kernel,
                         cudaFuncAttributeMaxDynamicSharedMemorySize, SMEM_BYTES);
    decoder_kernel<<<nsm, NT, SMEM_BYTES>>>(p);
}